// round 11
// baseline (speedup 1.0000x reference)
#include <cuda_runtime.h>
#include <cuda_fp16.h>

// Problem constants (BOWRegressionMulti: T=200, B=1024, V=50000, L=512, PAD=1)
#define T_TOK 200
#define B_SZ  1024
#define V_SZ  50000
#define L_SZ  512
#define PAD_TOK 1
#define V_WORDS 1563                     // ceil(V/32)

#define VTILES 782                       // ceil(V/64)
#define HALF_T (VTILES * 4)              // 3128 transpose tiles per label-half
#define N_GCH  (B_SZ * 4)                // 4096 gather chunk items per half

// Static ordered work queue: [dedupe][T half0][G half0][T half1][G half1]
#define IT_B0 (B_SZ)                     // 1024
#define IT_C0 (IT_B0 + HALF_T)           // 4152
#define IT_D0 (IT_C0 + N_GCH)            // 8248
#define IT_E0 (IT_D0 + HALF_T)           // 11376
#define TOTAL (IT_E0 + N_GCH)            // 15472

#define GRID_BLKS 1184                   // 148 SMs x 8 blocks: all co-resident

// Scratch (static device globals — no allocs):
__device__ __half   g_Wt_h[(size_t)V_SZ * L_SZ];   // 51.2 MB transposed fp16 weights
__device__ unsigned g_toks[B_SZ][T_TOK];           // deduped uint2-offsets (v*128)
__device__ int      g_cnt[B_SZ];
__device__ float4   g_part[B_SZ][2][4][64];        // 8 MB chunk partials
__device__ int      c_init, c_t0, c_t1, c_done;    // progress counters (zero-init)
__device__ int      c_row[B_SZ][2];                // per-(row,half) chunk counters

__global__ __launch_bounds__(256, 8) void bow_fused_kernel(
    const float* __restrict__ W,         // [L, V] f32
    const int*   __restrict__ text,      // [T, B] int32
    const float* __restrict__ bias,      // [L]
    float*       __restrict__ out)       // [B, L]
{
    __shared__ float s_f[64 * 65];       // 16.64 KB, reused by every role
    __shared__ int   s_cnt;
    __shared__ int   s_flag;

    const int tid = threadIdx.x;

    for (int it = blockIdx.x; it < TOTAL; it += GRID_BLKS) {
        __syncthreads();                 // smem reuse guard between items

        if (it < IT_B0) {
            // ============ dedupe item: row b ============
            const int b = it;
            unsigned int* bitmap = (unsigned int*)s_f;
            for (int i = tid; i < V_WORDS; i += 256) bitmap[i] = 0u;
            if (tid == 0) s_cnt = 0;
            __syncthreads();
            if (tid < T_TOK) {
                int v = text[(size_t)tid * B_SZ + b];
                if (v != PAD_TOK && (unsigned)v < (unsigned)V_SZ) {
                    unsigned int bit = 1u << (v & 31);
                    unsigned int old = atomicOr(&bitmap[v >> 5], bit);
                    if (!(old & bit)) {
                        int idx = atomicAdd(&s_cnt, 1);
                        g_toks[b][idx] = (unsigned)v * (L_SZ / 4);  // uint2 units
                    }
                }
            }
            __syncthreads();
            if (tid == 0) {
                g_cnt[b] = s_cnt;
                __threadfence();
                atomicAdd(&c_init, 1);
            }
        } else if (it < IT_C0 || (it >= IT_D0 && it < IT_E0)) {
            // ============ transpose item ============
            const int h     = (it >= IT_D0);
            const int local = h ? (it - IT_D0) : (it - IT_B0);
            const int v0 = (local % VTILES) * 64;
            const int l0 = h * 256 + (local / VTILES) * 64;
            {
                const int tx = tid & 15;
                const int ty = tid >> 4;
                const int v  = v0 + tx * 4;
                #pragma unroll
                for (int p = 0; p < 4; p++) {
                    const int l = ty + p * 16;
                    float4 val = make_float4(0.f, 0.f, 0.f, 0.f);
                    if (v < V_SZ) {
                        val = __ldcs((const float4*)(W + (size_t)(l0 + l) * V_SZ + v));
                    }
                    s_f[l * 65 + tx * 4 + 0] = val.x;
                    s_f[l * 65 + tx * 4 + 1] = val.y;
                    s_f[l * 65 + tx * 4 + 2] = val.z;
                    s_f[l * 65 + tx * 4 + 3] = val.w;
                }
            }
            __syncthreads();
            {
                const int wx = tid & 7;
                const int wy = tid >> 3;
                #pragma unroll
                for (int p = 0; p < 2; p++) {
                    const int vr = wy + p * 32;
                    const int v  = v0 + vr;
                    if (v < V_SZ) {
                        const int lbase = wx * 8;
                        __half2 hh[4];
                        #pragma unroll
                        for (int k = 0; k < 4; k++) {
                            hh[k] = __floats2half2_rn(s_f[(lbase + 2 * k) * 65 + vr],
                                                      s_f[(lbase + 2 * k + 1) * 65 + vr]);
                        }
                        uint4 pkt;
                        pkt.x = *(unsigned int*)&hh[0];
                        pkt.y = *(unsigned int*)&hh[1];
                        pkt.z = *(unsigned int*)&hh[2];
                        pkt.w = *(unsigned int*)&hh[3];
                        *(uint4*)(g_Wt_h + (size_t)v * L_SZ + l0 + lbase) = pkt;
                    }
                }
            }
            __syncthreads();
            if (tid == 0) {
                __threadfence();
                atomicAdd(h ? &c_t1 : &c_t0, 1);
            }
        } else {
            // ============ gather chunk item: (row r, half h, chunk q) ============
            const int h     = (it >= IT_E0);
            const int local = h ? (it - IT_E0) : (it - IT_C0);
            const int r = local >> 2;
            const int q = local & 3;

            // Gate: dedupe + this half's transpose complete.
            if (tid == 0) {
                volatile int* pi = &c_init;
                volatile int* pt = h ? &c_t1 : &c_t0;
                while (*pi < B_SZ)   __nanosleep(128);
                while (*pt < HALF_T) __nanosleep(128);
                __threadfence();
            }
            __syncthreads();

            unsigned* s_offs = (unsigned*)s_f;              // [0,200) words
            float4*   s_part = (float4*)(s_f + 1024);       // 3*64 float4

            const int n = g_cnt[r];
            if (tid < T_TOK) s_offs[tid] = g_toks[r][tid];
            __syncthreads();

            const int g2 = tid >> 6;      // token sub-stream 0..3
            const int t2 = tid & 63;      // label group: labels h*256 + [4t2, 4t2+4)
            const int s  = (q << 2) | g2; // global stream 0..15
            const int m  = (n - s + 15) >> 4;

            const uint2* base = (const uint2*)g_Wt_h + (h << 6) + t2;

            float2 a0 = make_float2(0.f, 0.f);
            float2 a1 = make_float2(0.f, 0.f);
            float2 a2 = make_float2(0.f, 0.f);
            float2 a3 = make_float2(0.f, 0.f);

            int i = 0;
            for (; i + 8 <= m; i += 8) {
                const int jb = s + (i << 4);
                uint2 u0 = base[s_offs[jb +   0]];
                uint2 u1 = base[s_offs[jb +  16]];
                uint2 u2 = base[s_offs[jb +  32]];
                uint2 u3 = base[s_offs[jb +  48]];
                uint2 u4 = base[s_offs[jb +  64]];
                uint2 u5 = base[s_offs[jb +  80]];
                uint2 u6 = base[s_offs[jb +  96]];
                uint2 u7 = base[s_offs[jb + 112]];
                __half2 p0x = __hadd2(*(__half2*)&u0.x, *(__half2*)&u1.x);
                __half2 p0y = __hadd2(*(__half2*)&u0.y, *(__half2*)&u1.y);
                __half2 p1x = __hadd2(*(__half2*)&u2.x, *(__half2*)&u3.x);
                __half2 p1y = __hadd2(*(__half2*)&u2.y, *(__half2*)&u3.y);
                __half2 p2x = __hadd2(*(__half2*)&u4.x, *(__half2*)&u5.x);
                __half2 p2y = __hadd2(*(__half2*)&u4.y, *(__half2*)&u5.y);
                __half2 p3x = __hadd2(*(__half2*)&u6.x, *(__half2*)&u7.x);
                __half2 p3y = __hadd2(*(__half2*)&u6.y, *(__half2*)&u7.y);
                __half2 q0x = __hadd2(p0x, p1x);
                __half2 q0y = __hadd2(p0y, p1y);
                __half2 q1x = __hadd2(p2x, p3x);
                __half2 q1y = __hadd2(p2y, p3y);
                float2 f;
                f = __half22float2(q0x); a0.x += f.x; a0.y += f.y;
                f = __half22float2(q0y); a1.x += f.x; a1.y += f.y;
                f = __half22float2(q1x); a2.x += f.x; a2.y += f.y;
                f = __half22float2(q1y); a3.x += f.x; a3.y += f.y;
            }
            for (; i + 2 <= m; i += 2) {
                const int jb = s + (i << 4);
                uint2 u0 = base[s_offs[jb]];
                uint2 u1 = base[s_offs[jb + 16]];
                __half2 px = __hadd2(*(__half2*)&u0.x, *(__half2*)&u1.x);
                __half2 py = __hadd2(*(__half2*)&u0.y, *(__half2*)&u1.y);
                float2 f;
                f = __half22float2(px); a0.x += f.x; a0.y += f.y;
                f = __half22float2(py); a1.x += f.x; a1.y += f.y;
            }
            if (i < m) {
                uint2 u = base[s_offs[s + (i << 4)]];
                float2 f;
                f = __half22float2(*(__half2*)&u.x); a2.x += f.x; a2.y += f.y;
                f = __half22float2(*(__half2*)&u.y); a3.x += f.x; a3.y += f.y;
            }

            float4 s4;
            s4.x = a0.x + a2.x;
            s4.y = a0.y + a2.y;
            s4.z = a1.x + a3.x;
            s4.w = a1.y + a3.y;

            if (g2) s_part[(g2 - 1) * 64 + t2] = s4;
            __syncthreads();
            if (g2 == 0) {
                const float4 p1 = s_part[t2];
                const float4 p2 = s_part[64 + t2];
                const float4 p3 = s_part[128 + t2];
                float4 o;
                o.x = (s4.x + p1.x) + (p2.x + p3.x);
                o.y = (s4.y + p1.y) + (p2.y + p3.y);
                o.z = (s4.z + p1.z) + (p2.z + p3.z);
                o.w = (s4.w + p1.w) + (p2.w + p3.w);
                g_part[r][h][q][t2] = o;
            }
            __syncthreads();
            if (tid == 0) {
                __threadfence();
                int old = atomicAdd(&c_row[r][h], 1);
                s_flag = (old == 3);
                if (old == 3) __threadfence();   // acquire for partial reads
            }
            __syncthreads();
            if (s_flag && tid < 64) {
                // Last finisher combines (fixed order -> deterministic).
                const float4 b4 = ((const float4*)bias)[(h << 6) + tid];
                const float4 p0 = g_part[r][h][0][tid];
                const float4 p1 = g_part[r][h][1][tid];
                const float4 p2 = g_part[r][h][2][tid];
                const float4 p3 = g_part[r][h][3][tid];
                float4 o;
                o.x = b4.x + ((p0.x + p1.x) + (p2.x + p3.x));
                o.y = b4.y + ((p0.y + p1.y) + (p2.y + p3.y));
                o.z = b4.z + ((p0.z + p1.z) + (p2.z + p3.z));
                o.w = b4.w + ((p0.w + p1.w) + (p2.w + p3.w));
                ((float4*)out)[(size_t)r * 128 + (h << 6) + tid] = o;
            }
        }

        // ---- completion tracking + self-reset for graph replays ----
        __syncthreads();
        if (tid == 0) {
            int d = atomicAdd(&c_done, 1);
            s_flag = (d == TOTAL - 1);
        }
        __syncthreads();
        if (s_flag) {
            for (int i = tid; i < B_SZ * 2; i += 256) ((int*)c_row)[i] = 0;
            if (tid == 0) { c_init = 0; c_t0 = 0; c_t1 = 0; }
            __syncthreads();
            if (tid == 0) { __threadfence(); c_done = 0; }
        }
    }
}

// ---------------------------------------------------------------------------
// Launch: one fused kernel, static work queue, internal dependency gates.
// Inputs: [0] text int32 [T,B], [1] W f32 [L,V], [2] b f32 [L].
// ---------------------------------------------------------------------------
extern "C" void kernel_launch(void* const* d_in, const int* in_sizes, int n_in,
                              void* d_out, int out_size) {
    const int*   text = (const int*)d_in[0];
    const float* W    = (const float*)d_in[1];
    const float* bias = (const float*)d_in[2];
    float*       out  = (float*)d_out;

    bow_fused_kernel<<<GRID_BLKS, 256>>>(W, text, bias, out);
}

// round 12
// speedup vs baseline: 1.7096x; 1.7096x over previous
#include <cuda_runtime.h>
#include <cuda_fp16.h>

// Problem constants (BOWRegressionMulti: T=200, B=1024, V=50000, L=512, PAD=1)
#define T_TOK 200
#define B_SZ  1024
#define V_SZ  50000
#define L_SZ  512
#define PAD_TOK 1
#define V_WORDS 1563                       // ceil(V/32)

#define VTILES 782                         // ceil(V/64)
#define HALF_T (VTILES * 4)                // 3128 transpose tiles per label-half

// Scratch (static device globals — no allocs):
__device__ __half   g_Wt_h[(size_t)V_SZ * L_SZ];   // 51.2 MB transposed fp16 weights
__device__ unsigned g_toks[B_SZ][T_TOK];           // deduped uint2-offsets (v*128)
__device__ int      g_cnt[B_SZ];

// ---------------------------------------------------------------------------
// K1: prep(h) — transpose of label half h (labels [256h, 256h+256)).
// For h=0, extra blocks [HALF_T, HALF_T+B_SZ) also do per-row token dedupe.
// ---------------------------------------------------------------------------
__global__ __launch_bounds__(256) void bow_prep_kernel(
    const float* __restrict__ W,           // [L, V] f32
    const int*   __restrict__ text,        // [T, B] int32
    const int h)
{
    __shared__ float tile[64][65];         // 16.64 KB (transpose) / bitmap (dedupe)
    const int bid = blockIdx.x;
    const int tid = threadIdx.x;

    if (bid < HALF_T) {
        // ---------------- transpose role ----------------
        const int v0 = (bid % VTILES) * 64;
        const int l0 = h * 256 + (bid / VTILES) * 64;

        {
            const int tx = tid & 15;
            const int ty = tid >> 4;
            const int v  = v0 + tx * 4;
            #pragma unroll
            for (int p = 0; p < 4; p++) {
                const int l = ty + p * 16;
                float4 val = make_float4(0.f, 0.f, 0.f, 0.f);
                if (v < V_SZ) {
                    val = __ldcs((const float4*)(W + (size_t)(l0 + l) * V_SZ + v));
                }
                tile[l][tx * 4 + 0] = val.x;
                tile[l][tx * 4 + 1] = val.y;
                tile[l][tx * 4 + 2] = val.z;
                tile[l][tx * 4 + 3] = val.w;
            }
        }
        __syncthreads();

        {
            const int wx = tid & 7;
            const int wy = tid >> 3;
            #pragma unroll
            for (int p = 0; p < 2; p++) {
                const int vr = wy + p * 32;
                const int v  = v0 + vr;
                if (v < V_SZ) {
                    const int lbase = wx * 8;
                    __half2 hh[4];
                    #pragma unroll
                    for (int k = 0; k < 4; k++) {
                        hh[k] = __floats2half2_rn(tile[lbase + 2 * k][vr],
                                                  tile[lbase + 2 * k + 1][vr]);
                    }
                    uint4 pkt;
                    pkt.x = *(unsigned int*)&hh[0];
                    pkt.y = *(unsigned int*)&hh[1];
                    pkt.z = *(unsigned int*)&hh[2];
                    pkt.w = *(unsigned int*)&hh[3];
                    *(uint4*)(g_Wt_h + (size_t)v * L_SZ + l0 + lbase) = pkt;
                }
            }
        }
    } else {
        // ---------------- dedupe role (h==0 grid only) ----------------
        const int b = bid - HALF_T;
        unsigned int* bitmap = (unsigned int*)&tile[0][0];
        __shared__ int cnt;

        for (int i = tid; i < V_WORDS; i += 256) bitmap[i] = 0u;
        if (tid == 0) cnt = 0;
        __syncthreads();

        if (tid < T_TOK) {
            int v = text[(size_t)tid * B_SZ + b];
            if (v != PAD_TOK && (unsigned)v < (unsigned)V_SZ) {
                unsigned int bit = 1u << (v & 31);
                unsigned int old = atomicOr(&bitmap[v >> 5], bit);
                if (!(old & bit)) {
                    int idx = atomicAdd(&cnt, 1);
                    g_toks[b][idx] = (unsigned)v * (L_SZ / 4);  // uint2-offset units
                }
            }
        }
        __syncthreads();
        if (tid == 0) g_cnt[b] = cnt;
    }
}

// ---------------------------------------------------------------------------
// K2: gather(h) — labels [256h, 256h+256) for all rows. One block = one row.
// 256 threads: g = tid>>6 = token stream (0..3), t = tid&63 owns labels
// 256h + [4t, 4t+4) via one uint2 (8B) load per token. Depth-2 fp16 tree,
// fp32 accumulation; 4 stream-partials combined in smem, fixed order.
// ---------------------------------------------------------------------------
__global__ __launch_bounds__(256, 8) void bow_gather_kernel(
    const float* __restrict__ bias,        // [L]
    float* __restrict__ out,               // [B, L]
    const int h)
{
    __shared__ unsigned offs[T_TOK];
    __shared__ float4 part[3][64];         // streams 1..3 partials (3 KB)

    const int b   = blockIdx.x;
    const int tid = threadIdx.x;
    const int g   = tid >> 6;              // token stream 0..3
    const int t   = tid & 63;              // label group within half

    const int n = g_cnt[b];
    if (tid < T_TOK) offs[tid] = g_toks[b][tid];
    __syncthreads();

    // Per-thread base into this half's 64 uint2 per row.
    const uint2* base = (const uint2*)g_Wt_h + (h << 6) + t;

    const int m = (n - g + 3) >> 2;        // count of own-stream tokens

    float2 a0 = make_float2(0.f, 0.f);
    float2 a1 = make_float2(0.f, 0.f);
    float2 a2 = make_float2(0.f, 0.f);
    float2 a3 = make_float2(0.f, 0.f);

    int i = 0;
    for (; i + 8 <= m; i += 8) {
        const int jb = (i << 2) + g;
        uint2 u0 = base[offs[jb +  0]];
        uint2 u1 = base[offs[jb +  4]];
        uint2 u2 = base[offs[jb +  8]];
        uint2 u3 = base[offs[jb + 12]];
        uint2 u4 = base[offs[jb + 16]];
        uint2 u5 = base[offs[jb + 20]];
        uint2 u6 = base[offs[jb + 24]];
        uint2 u7 = base[offs[jb + 28]];
        __half2 p0x = __hadd2(*(__half2*)&u0.x, *(__half2*)&u1.x);
        __half2 p0y = __hadd2(*(__half2*)&u0.y, *(__half2*)&u1.y);
        __half2 p1x = __hadd2(*(__half2*)&u2.x, *(__half2*)&u3.x);
        __half2 p1y = __hadd2(*(__half2*)&u2.y, *(__half2*)&u3.y);
        __half2 p2x = __hadd2(*(__half2*)&u4.x, *(__half2*)&u5.x);
        __half2 p2y = __hadd2(*(__half2*)&u4.y, *(__half2*)&u5.y);
        __half2 p3x = __hadd2(*(__half2*)&u6.x, *(__half2*)&u7.x);
        __half2 p3y = __hadd2(*(__half2*)&u6.y, *(__half2*)&u7.y);
        __half2 q0x = __hadd2(p0x, p1x);
        __half2 q0y = __hadd2(p0y, p1y);
        __half2 q1x = __hadd2(p2x, p3x);
        __half2 q1y = __hadd2(p2y, p3y);
        float2 f;
        f = __half22float2(q0x); a0.x += f.x; a0.y += f.y;
        f = __half22float2(q0y); a1.x += f.x; a1.y += f.y;
        f = __half22float2(q1x); a2.x += f.x; a2.y += f.y;
        f = __half22float2(q1y); a3.x += f.x; a3.y += f.y;
    }
    for (; i + 2 <= m; i += 2) {
        const int jb = (i << 2) + g;
        uint2 u0 = base[offs[jb]];
        uint2 u1 = base[offs[jb + 4]];
        __half2 px = __hadd2(*(__half2*)&u0.x, *(__half2*)&u1.x);
        __half2 py = __hadd2(*(__half2*)&u0.y, *(__half2*)&u1.y);
        float2 f;
        f = __half22float2(px); a0.x += f.x; a0.y += f.y;
        f = __half22float2(py); a1.x += f.x; a1.y += f.y;
    }
    if (i < m) {
        uint2 u = base[offs[(i << 2) + g]];
        float2 f;
        f = __half22float2(*(__half2*)&u.x); a2.x += f.x; a2.y += f.y;
        f = __half22float2(*(__half2*)&u.y); a3.x += f.x; a3.y += f.y;
    }

    float4 s4;
    s4.x = a0.x + a2.x;
    s4.y = a0.y + a2.y;
    s4.z = a1.x + a3.x;
    s4.w = a1.y + a3.y;

    if (g) part[g - 1][t] = s4;
    __syncthreads();

    if (g == 0) {
        const float4 bs = ((const float4*)bias)[(h << 6) + t];
        const float4 p1 = part[0][t];
        const float4 p2 = part[1][t];
        const float4 p3 = part[2][t];
        float4 r;
        r.x = bs.x + ((s4.x + p1.x) + (p2.x + p3.x));
        r.y = bs.y + ((s4.y + p1.y) + (p2.y + p3.y));
        r.z = bs.z + ((s4.z + p1.z) + (p2.z + p3.z));
        r.w = bs.w + ((s4.w + p1.w) + (p2.w + p3.w));
        ((float4*)out)[(size_t)b * 128 + (h << 6) + t] = r;
    }
}

// ---------------------------------------------------------------------------
// Launch: fork-join overlap.
//   main:  prep0(+dedupe) ──fork──> prep1 ─> gather1 ──join──>
//   s2:                      └────> gather0 ──────────────┘
// gather0 (L2-bound) overlaps prep1 (DRAM-bound). Streams/events created
// once on the first (uncaptured) call; per-call work is identical.
// Inputs: [0] text int32 [T,B], [1] W f32 [L,V], [2] b f32 [L].
// ---------------------------------------------------------------------------
extern "C" void kernel_launch(void* const* d_in, const int* in_sizes, int n_in,
                              void* d_out, int out_size) {
    const int*   text = (const int*)d_in[0];
    const float* W    = (const float*)d_in[1];
    const float* bias = (const float*)d_in[2];
    float*       out  = (float*)d_out;

    static cudaStream_t s2 = 0;
    static cudaEvent_t  ev_fork = 0, ev_join = 0;
    if (s2 == 0) {
        cudaStreamCreateWithFlags(&s2, cudaStreamNonBlocking);
        cudaEventCreateWithFlags(&ev_fork, cudaEventDisableTiming);
        cudaEventCreateWithFlags(&ev_join, cudaEventDisableTiming);
    }

    // prep half0 + dedupe (main stream)
    bow_prep_kernel<<<HALF_T + B_SZ, 256>>>(W, text, 0);

    // fork: gather half0 on s2, concurrent with prep half1 on main
    cudaEventRecord(ev_fork, 0);
    cudaStreamWaitEvent(s2, ev_fork, 0);
    bow_gather_kernel<<<B_SZ, 256, 0, s2>>>(bias, out, 0);
    cudaEventRecord(ev_join, s2);

    bow_prep_kernel<<<HALF_T, 256>>>(W, text, 1);
    bow_gather_kernel<<<B_SZ, 256>>>(bias, out, 1);

    // join: main stream waits for gather half0
    cudaStreamWaitEvent(0, ev_join, 0);
}

// round 13
// speedup vs baseline: 2.1429x; 1.2534x over previous
#include <cuda_runtime.h>
#include <cuda_fp16.h>

// Problem constants (BOWRegressionMulti: T=200, B=1024, V=50000, L=512, PAD=1)
#define T_TOK 200
#define B_SZ  1024
#define V_SZ  50000
#define L_SZ  512
#define PAD_TOK 1
#define V_WORDS 1563                       // ceil(V/32)

#define VTILES 782                         // ceil(V/64)
#define LTILES (L_SZ / 64)                 // 8
#define TR_BLOCKS (VTILES * LTILES)        // 6256 transpose blocks

// Scratch (static device globals — no allocs):
__device__ __half   g_Wt_h[(size_t)V_SZ * L_SZ];   // 51.2 MB transposed fp16 weights
__device__ unsigned g_toks[B_SZ][T_TOK];           // deduped uint2-offsets (v*128)
__device__ int      g_cnt[B_SZ];

// ---------------------------------------------------------------------------
// K1 (fused prep): blocks [0, TR_BLOCKS) transpose W[L,V] f32 -> Wt[V,L] f16
// with HALF-PRECISION smem staging (convert during read; half the smem
// traffic; stride-69 pad -> conflict-free write-phase LDS). Blocks
// [TR_BLOCKS, TR_BLOCKS+B_SZ) do per-row token dedupe in the same smem union.
// ---------------------------------------------------------------------------
__global__ __launch_bounds__(256) void bow_prep_kernel(
    const float* __restrict__ W,           // [L, V] f32
    const int*   __restrict__ text)        // [T, B] int32
{
    __shared__ unsigned s_buf[32 * 69];    // 8.83 KB: [lp][v] half2 tile / bitmap
    const int bid = blockIdx.x;
    const int tid = threadIdx.x;

    if (bid < TR_BLOCKS) {
        // ---------------- transpose role ----------------
        const int v0 = (bid % VTILES) * 64;
        const int l0 = (bid / VTILES) * 64;
        const int tx = tid & 15;
        const int ty = tid >> 4;
        const int v  = v0 + tx * 4;        // V%4==0 -> all-or-none per float4

        // Read: two adjacent l-rows per thread, convert to half2 on the fly.
        // s_buf[lp*69 + vi] = half2( W[l0+2lp][v0+vi], W[l0+2lp+1][v0+vi] )
        #pragma unroll
        for (int p = 0; p < 2; p++) {
            const int lp = ty + p * 16;            // label-pair index 0..31
            const int l  = l0 + 2 * lp;
            if (v < V_SZ) {
                const float4 ra = __ldcs((const float4*)(W + (size_t)l       * V_SZ + v));
                const float4 rb = __ldcs((const float4*)(W + (size_t)(l + 1) * V_SZ + v));
                __half2 h0 = __floats2half2_rn(ra.x, rb.x);
                __half2 h1 = __floats2half2_rn(ra.y, rb.y);
                __half2 h2 = __floats2half2_rn(ra.z, rb.z);
                __half2 h3 = __floats2half2_rn(ra.w, rb.w);
                s_buf[lp * 69 + tx * 4 + 0] = *(unsigned*)&h0;
                s_buf[lp * 69 + tx * 4 + 1] = *(unsigned*)&h1;
                s_buf[lp * 69 + tx * 4 + 2] = *(unsigned*)&h2;
                s_buf[lp * 69 + tx * 4 + 3] = *(unsigned*)&h3;
            }
        }
        __syncthreads();

        // Write: item k -> (v = k>>3, w = k&7): uint4 = 4 half2 = labels
        // l0+8w .. l0+8w+7 of Wt row v0+v. Stride-69 LDS is conflict-free.
        #pragma unroll
        for (int k = tid; k < 512; k += 256) {
            const int vr = k >> 3;
            const int w  = k & 7;
            if (v0 + vr < V_SZ) {
                uint4 pkt;
                pkt.x = s_buf[(4 * w + 0) * 69 + vr];
                pkt.y = s_buf[(4 * w + 1) * 69 + vr];
                pkt.z = s_buf[(4 * w + 2) * 69 + vr];
                pkt.w = s_buf[(4 * w + 3) * 69 + vr];
                *(uint4*)(g_Wt_h + (size_t)(v0 + vr) * L_SZ + l0 + 8 * w) = pkt;
            }
        }
    } else {
        // ---------------- dedupe role ----------------
        const int b = bid - TR_BLOCKS;
        unsigned int* bitmap = s_buf;      // 1563 words fit in 2208-word buffer
        __shared__ int cnt;

        for (int i = tid; i < V_WORDS; i += 256) bitmap[i] = 0u;
        if (tid == 0) cnt = 0;
        __syncthreads();

        if (tid < T_TOK) {
            int v = text[(size_t)tid * B_SZ + b];
            if (v != PAD_TOK && (unsigned)v < (unsigned)V_SZ) {
                unsigned int bit = 1u << (v & 31);
                unsigned int old = atomicOr(&bitmap[v >> 5], bit);
                if (!(old & bit)) {
                    int idx = atomicAdd(&cnt, 1);
                    g_toks[b][idx] = (unsigned)v * (L_SZ / 4);  // uint2-offset units
                }
            }
        }
        __syncthreads();
        if (tid == 0) g_cnt[b] = cnt;
    }
}

// ---------------------------------------------------------------------------
// K2: gather (R10, proven 20.3us @ ~88% LTS ceiling). One block = one row.
// 256 threads: g = tid>>7 = token parity, t = tid&127 owns labels [4t, 4t+4)
// via one uint2 (8B) load per token. Depth-2 fp16 pre-add tree, fp32
// accumulation; parity-1 partials staged in smem, combined with bias.
// __launch_bounds__(256, 8) pins regs <= 32.
// ---------------------------------------------------------------------------
__global__ __launch_bounds__(256, 8) void bow_gather_kernel(
    const float* __restrict__ bias,        // [L]
    float* __restrict__ out)               // [B, L]
{
    __shared__ unsigned offs[T_TOK];
    __shared__ float4 part[128];           // parity-1 partials (2 KB)

    const int b   = blockIdx.x;
    const int tid = threadIdx.x;
    const int g   = tid >> 7;              // token parity
    const int t   = tid & 127;             // label group: labels [4t, 4t+4)

    const int n = g_cnt[b];
    if (tid < T_TOK) offs[tid] = g_toks[b][tid];
    __syncthreads();

    // Per-thread base: address = base + off*8 -> single IMAD.WIDE per load.
    const uint2* Wt_t = (const uint2*)g_Wt_h + t;

    const int m = (n - g + 1) >> 1;        // count of own-parity tokens

    float2 a0 = make_float2(0.f, 0.f);
    float2 a1 = make_float2(0.f, 0.f);
    float2 a2 = make_float2(0.f, 0.f);
    float2 a3 = make_float2(0.f, 0.f);

    int i = 0;
    for (; i + 8 <= m; i += 8) {
        uint2 u0 = Wt_t[offs[2 * (i + 0) + g]];
        uint2 u1 = Wt_t[offs[2 * (i + 1) + g]];
        uint2 u2 = Wt_t[offs[2 * (i + 2) + g]];
        uint2 u3 = Wt_t[offs[2 * (i + 3) + g]];
        uint2 u4 = Wt_t[offs[2 * (i + 4) + g]];
        uint2 u5 = Wt_t[offs[2 * (i + 5) + g]];
        uint2 u6 = Wt_t[offs[2 * (i + 6) + g]];
        uint2 u7 = Wt_t[offs[2 * (i + 7) + g]];
        __half2 p0x = __hadd2(*(__half2*)&u0.x, *(__half2*)&u1.x);
        __half2 p0y = __hadd2(*(__half2*)&u0.y, *(__half2*)&u1.y);
        __half2 p1x = __hadd2(*(__half2*)&u2.x, *(__half2*)&u3.x);
        __half2 p1y = __hadd2(*(__half2*)&u2.y, *(__half2*)&u3.y);
        __half2 p2x = __hadd2(*(__half2*)&u4.x, *(__half2*)&u5.x);
        __half2 p2y = __hadd2(*(__half2*)&u4.y, *(__half2*)&u5.y);
        __half2 p3x = __hadd2(*(__half2*)&u6.x, *(__half2*)&u7.x);
        __half2 p3y = __hadd2(*(__half2*)&u6.y, *(__half2*)&u7.y);
        __half2 q0x = __hadd2(p0x, p1x);
        __half2 q0y = __hadd2(p0y, p1y);
        __half2 q1x = __hadd2(p2x, p3x);
        __half2 q1y = __hadd2(p2y, p3y);
        float2 f;
        f = __half22float2(q0x); a0.x += f.x; a0.y += f.y;
        f = __half22float2(q0y); a1.x += f.x; a1.y += f.y;
        f = __half22float2(q1x); a2.x += f.x; a2.y += f.y;
        f = __half22float2(q1y); a3.x += f.x; a3.y += f.y;
    }
    for (; i + 2 <= m; i += 2) {
        uint2 u0 = Wt_t[offs[2 * (i + 0) + g]];
        uint2 u1 = Wt_t[offs[2 * (i + 1) + g]];
        __half2 px = __hadd2(*(__half2*)&u0.x, *(__half2*)&u1.x);
        __half2 py = __hadd2(*(__half2*)&u0.y, *(__half2*)&u1.y);
        float2 f;
        f = __half22float2(px); a0.x += f.x; a0.y += f.y;
        f = __half22float2(py); a1.x += f.x; a1.y += f.y;
    }
    if (i < m) {
        uint2 u = Wt_t[offs[2 * i + g]];
        float2 f;
        f = __half22float2(*(__half2*)&u.x); a2.x += f.x; a2.y += f.y;
        f = __half22float2(*(__half2*)&u.y); a3.x += f.x; a3.y += f.y;
    }

    float4 s;
    s.x = a0.x + a2.x;
    s.y = a0.y + a2.y;
    s.z = a1.x + a3.x;
    s.w = a1.y + a3.y;

    if (g == 1) part[t] = s;
    __syncthreads();

    if (g == 0) {
        const float4 bs = ((const float4*)bias)[t];
        const float4 p  = part[t];
        float4 r;
        r.x = bs.x + s.x + p.x;
        r.y = bs.y + s.y + p.y;
        r.z = bs.z + s.z + p.z;
        r.w = bs.w + s.w + p.w;
        ((float4*)out)[(size_t)b * (L_SZ / 4) + t] = r;
    }
}

// ---------------------------------------------------------------------------
// Launch: fused prep (transpose + dedupe) then gather. Graph-capturable.
// Inputs: [0] text int32 [T,B], [1] W f32 [L,V], [2] b f32 [L].
// ---------------------------------------------------------------------------
extern "C" void kernel_launch(void* const* d_in, const int* in_sizes, int n_in,
                              void* d_out, int out_size) {
    const int*   text = (const int*)d_in[0];
    const float* W    = (const float*)d_in[1];
    const float* bias = (const float*)d_in[2];
    float*       out  = (float*)d_out;

    bow_prep_kernel<<<TR_BLOCKS + B_SZ, 256>>>(W, text);
    bow_gather_kernel<<<B_SZ, 256>>>(bias, out);
}